// round 6
// baseline (speedup 1.0000x reference)
#include <cuda_runtime.h>

#define NB 8
#define NS 4096
#define NH 8
#define ND 128
#define ROW (NH * ND)                 // 1024 floats per token-row
#define VPR (ROW / 4)                 // 256 float4 per row
#define MAX_TOTAL (NB * NS)           // 32768 rows per cache
#define CACHE_F (MAX_TOTAL * ROW)     // floats per cache
#define CACHE_V (MAX_TOTAL * VPR)     // 8388608 float4 per cache
#define TOTAL_V (2 * CACHE_V)         // 16777216 float4
#define THREADS 256
#define F4_PER_WARP 128               // 4 float4 per thread, warp-interleaved
#define WARPS_PER_BLOCK (THREADS / 32)
#define NUM_TILES (TOTAL_V / F4_PER_WARP)    // 131072 warp-tiles
#define BLOCKS (148 * 8)              // one full wave, persistent grid-stride

// Persistent version of the R5 kernel: grid sized to exactly one wave
// (148 SMs x 8 CTAs), each warp grid-strides over 128-float4 warp-tiles.
// Same per-tile access pattern as R5: lane l handles base + {0,32,64,96} + l,
// fully coalesced LDG.128/STG.128 with .cs streaming hints, MLP=4.
__global__ void __launch_bounds__(THREADS) pack_kernel(
    const float4* __restrict__ k_src,
    const float4* __restrict__ v_src,
    const int* __restrict__ seq_lens,
    float4* __restrict__ out)
{
    __shared__ int cs[NB + 1];
    if (threadIdx.x == 0) {
        int c = 0;
        cs[0] = 0;
        #pragma unroll
        for (int i = 0; i < NB; i++) { c += __ldg(seq_lens + i); cs[i + 1] = c; }
    }
    __syncthreads();

    if (blockIdx.x == 0 && threadIdx.x == 0) {
        float* seq_out = (float*)out + 2 * (long long)CACHE_F;  // [NB]
        float* cum_out = seq_out + NB;                           // [NB+1]
        #pragma unroll
        for (int i = 0; i < NB; i++) seq_out[i] = (float)(cs[i + 1] - cs[i]);
        #pragma unroll
        for (int i = 0; i <= NB; i++) cum_out[i] = (float)cs[i];
    }

    const int lane  = threadIdx.x & 31;
    const int warp0 = blockIdx.x * WARPS_PER_BLOCK + (threadIdx.x >> 5);
    const int wstride = BLOCKS * WARPS_PER_BLOCK;   // total warps in grid
    const int total = cs[NB];

    for (int w = warp0; w < NUM_TILES; w += wstride) {
        int base  = w * F4_PER_WARP;                // tile's first float4 index
        int which = (base >= CACHE_V) ? 1 : 0;      // whole tile in one cache
        int j   = base - which * CACHE_V;
        int row = j >> 8;                            // token-row
        int col = (j & (VPR - 1)) + lane;            // 0 or 128, plus lane

        float4 v0, v1, v2, v3;
        if (row < total) {
            int b = 0;
            #pragma unroll
            for (int bb = 1; bb < NB; bb++)
                if (row >= cs[bb]) b = bb;
            int t = row - cs[b];
            const float4* src = (which ? v_src : k_src)
                              + (long long)(b * NS + t) * VPR + col;
            v0 = __ldcs(src +  0);
            v1 = __ldcs(src + 32);
            v2 = __ldcs(src + 64);
            v3 = __ldcs(src + 96);
        } else {
            v0 = v1 = v2 = v3 = make_float4(0.f, 0.f, 0.f, 0.f);
        }

        float4* dst = out + base + lane;
        __stcs(dst +  0, v0);
        __stcs(dst + 32, v1);
        __stcs(dst + 64, v2);
        __stcs(dst + 96, v3);
    }
}

extern "C" void kernel_launch(void* const* d_in, const int* in_sizes, int n_in,
                              void* d_out, int out_size) {
    const float4* key_states   = (const float4*)d_in[0];
    const float4* value_states = (const float4*)d_in[1];
    const int*    seq_lens     = (const int*)d_in[2];

    pack_kernel<<<BLOCKS, THREADS>>>(key_states, value_states, seq_lens,
                                     (float4*)d_out);
}

// round 7
// speedup vs baseline: 1.1863x; 1.1863x over previous
#include <cuda_runtime.h>

#define NB 8
#define NS 4096
#define NH 8
#define ND 128
#define ROW (NH * ND)                 // 1024 floats per token-row
#define VPR (ROW / 4)                 // 256 float4 per row
#define MAX_TOTAL (NB * NS)           // 32768 rows per cache
#define CACHE_F (MAX_TOTAL * ROW)     // floats per cache
#define CACHE_V (MAX_TOTAL * VPR)     // 8388608 float4 per cache
#define TOTAL_V (2 * CACHE_V)         // 16777216 float4
#define THREADS 256
#define F4_PER_WARP 128               // 4 float4 per thread, warp-interleaved
#define WARPS_PER_BLOCK (THREADS / 32)
#define BLOCKS (TOTAL_V / (F4_PER_WARP * WARPS_PER_BLOCK))   // 16384

// R5 layout (best) + warp-parallel cumsum: lanes 0-7 of warp 0 load seq_lens
// concurrently (one L2 round-trip instead of an 8-load serial chain), then a
// shuffle inclusive scan produces the 9-entry cumsum. Main body unchanged:
// each warp owns 128 consecutive float4 (half a token-row); lane l handles
// base + {0,32,64,96} + l -> fully coalesced LDG.128/STG.128, .cs hints, MLP=4.
__global__ void __launch_bounds__(THREADS) pack_kernel(
    const float4* __restrict__ k_src,
    const float4* __restrict__ v_src,
    const int* __restrict__ seq_lens,
    float4* __restrict__ out)
{
    __shared__ int cs[NB + 1];
    if (threadIdx.x < 32) {
        int lane = threadIdx.x;
        int v = (lane < NB) ? __ldg(seq_lens + lane) : 0;
        // inclusive scan over lanes 0..7
        #pragma unroll
        for (int off = 1; off < NB; off <<= 1) {
            int n = __shfl_up_sync(0xffffffffu, v, off);
            if (lane >= off) v += n;
        }
        if (lane == 0) cs[0] = 0;
        if (lane < NB) cs[lane + 1] = v;
    }
    __syncthreads();

    if (blockIdx.x == 0 && threadIdx.x == 0) {
        float* seq_out = (float*)out + 2 * (long long)CACHE_F;  // [NB]
        float* cum_out = seq_out + NB;                           // [NB+1]
        #pragma unroll
        for (int i = 0; i < NB; i++) seq_out[i] = (float)(cs[i + 1] - cs[i]);
        #pragma unroll
        for (int i = 0; i <= NB; i++) cum_out[i] = (float)cs[i];
    }

    int lane = threadIdx.x & 31;
    int gw   = blockIdx.x * WARPS_PER_BLOCK + (threadIdx.x >> 5);
    int base = gw * F4_PER_WARP;                  // warp's first float4 index

    int which = (base >= CACHE_V) ? 1 : 0;        // whole warp in one cache
    int j   = base - which * CACHE_V;
    int row = j >> 8;                              // token-row (shared by all 4 elems)
    int col = (j & (VPR - 1)) + lane;              // 0 or 128, plus lane

    float4 v0, v1, v2, v3;
    if (row < cs[NB]) {
        int b = 0;
        #pragma unroll
        for (int bb = 1; bb < NB; bb++)
            if (row >= cs[bb]) b = bb;
        int t = row - cs[b];
        const float4* src = (which ? v_src : k_src)
                          + (long long)(b * NS + t) * VPR + col;
        v0 = __ldcs(src +  0);
        v1 = __ldcs(src + 32);
        v2 = __ldcs(src + 64);
        v3 = __ldcs(src + 96);
    } else {
        v0 = v1 = v2 = v3 = make_float4(0.f, 0.f, 0.f, 0.f);
    }

    float4* dst = out + base + lane;
    __stcs(dst +  0, v0);
    __stcs(dst + 32, v1);
    __stcs(dst + 64, v2);
    __stcs(dst + 96, v3);
}

extern "C" void kernel_launch(void* const* d_in, const int* in_sizes, int n_in,
                              void* d_out, int out_size) {
    const float4* key_states   = (const float4*)d_in[0];
    const float4* value_states = (const float4*)d_in[1];
    const int*    seq_lens     = (const int*)d_in[2];

    pack_kernel<<<BLOCKS, THREADS>>>(key_states, value_states, seq_lens,
                                     (float4*)d_out);
}